// round 15
// baseline (speedup 1.0000x reference)
#include <cuda_runtime.h>
#include <math.h>

#define BB  2
#define PP  64
#define NBB 64
#define TT  256
#define VV  32
#define HH  4
#define AO  32
#define LAT 64
#define RS  68
#define ROWS 33
#define TS  (32*RS)     // 2176 floats per 32-row tile
#define VST 68

typedef unsigned long long ull;

__device__ float g_bterm[BB*NBB*LAT];

__device__ __forceinline__ float tanh_fast(float x) {
    float y; asm("tanh.approx.f32 %0,%1;" : "=f"(y) : "f"(x)); return y;
}
__device__ __forceinline__ ull packdup(float x) {
    ull r; asm("mov.b64 %0,{%1,%1};" : "=l"(r) : "f"(x)); return r;
}
__device__ __forceinline__ void fma2(ull& d, ull a, ull b) {
    asm("fma.rn.f32x2 %0,%1,%2,%0;" : "+l"(d) : "l"(a), "l"(b));
}
__device__ __forceinline__ float2 unpk(ull a) {
    float2 f; asm("mov.b64 {%0,%1},%2;" : "=f"(f.x), "=f"(f.y) : "l"(a)); return f;
}

// ---------------- prep: boundary term table ----------------------------------
__global__ void prep_kernel(const float* __restrict__ bcoords,
                            const float* __restrict__ W1) {
    int bn = blockIdx.x, d = threadIdx.x;
    const float* bc = bcoords + bn * 4;
    g_bterm[bn*LAT + d] = bc[0]*W1[4*LAT+d] + bc[1]*W1[5*LAT+d]
                        + bc[2]*W1[6*LAT+d] + bc[3]*W1[7*LAT+d];
}

// ---------------- fused kernel helpers ---------------------------------------
template<bool ADD>
__device__ __forceinline__ void gemm8(const float* __restrict__ src, float* __restrict__ dst,
                                      const float* __restrict__ W, const float* __restrict__ bias,
                                      int r, int dg)
{
    ull acc[8][4];
    const ulonglong2* bp = (const ulonglong2*)(bias + dg);
    ulonglong2 b01 = bp[0], b23 = bp[1];
#pragma unroll
    for (int t = 0; t < 8; t++) { acc[t][0]=b01.x; acc[t][1]=b01.y; acc[t][2]=b23.x; acc[t][3]=b23.y; }
    const float* row = src + r*RS;
#pragma unroll 4
    for (int c4 = 0; c4 < 16; c4++) {
        float4 x[8];
#pragma unroll
        for (int t = 0; t < 8; t++) x[t] = *(const float4*)(row + t*TS + c4*4);
#pragma unroll
        for (int cc = 0; cc < 4; cc++) {
            const ulonglong2* w = (const ulonglong2*)(W + (c4*4+cc)*LAT + dg);
            ulonglong2 w01 = w[0], w23 = w[1];
#pragma unroll
            for (int t = 0; t < 8; t++) {
                float xv = (cc==0)?x[t].x:(cc==1)?x[t].y:(cc==2)?x[t].z:x[t].w;
                ull p = packdup(xv);
                fma2(acc[t][0], p, w01.x); fma2(acc[t][1], p, w01.y);
                fma2(acc[t][2], p, w23.x); fma2(acc[t][3], p, w23.y);
            }
        }
    }
#pragma unroll
    for (int t = 0; t < 8; t++) {
        float* o = dst + t*TS + r*RS + dg;
        float2 f0=unpk(acc[t][0]), f1=unpk(acc[t][1]), f2=unpk(acc[t][2]), f3=unpk(acc[t][3]);
        if (ADD) {
            float4 e0 = *(float4*)o, e1 = *(float4*)(o+4);
            e0.x += tanh_fast(f0.x); e0.y += tanh_fast(f0.y); e0.z += tanh_fast(f1.x); e0.w += tanh_fast(f1.y);
            e1.x += tanh_fast(f2.x); e1.y += tanh_fast(f2.y); e1.z += tanh_fast(f3.x); e1.w += tanh_fast(f3.y);
            *(float4*)o = e0; *(float4*)(o+4) = e1;
        } else {
            float4 e0 = make_float4(tanh_fast(f0.x),tanh_fast(f0.y),tanh_fast(f1.x),tanh_fast(f1.y));
            float4 e1 = make_float4(tanh_fast(f2.x),tanh_fast(f2.y),tanh_fast(f3.x),tanh_fast(f3.y));
            *(float4*)o = e0; *(float4*)(o+4) = e1;
        }
    }
}

// multi-row mix with transposed SK table (float4 loads)
__device__ __forceinline__ void mixMR(const float* __restrict__ src, float* __restrict__ dst,
                                      const float* __restrict__ SKt, int rg, int tp, int dgm)
{
    ull acc[4][2][4];
#pragma unroll
    for (int j = 0; j < 4; j++)
#pragma unroll
        for (int t = 0; t < 2; t++) {
            acc[j][t][0]=0; acc[j][t][1]=0; acc[j][t][2]=0; acc[j][t][3]=0;
        }
    const float* s0 = src + (2*tp)*TS + dgm;
    const float* s1 = src + (2*tp+1)*TS + dgm;
#pragma unroll 4
    for (int c = 0; c < VV; c++) {
        float4 s4 = *(const float4*)(SKt + c*36 + 4*rg);
        ulonglong2 xa0 = *(const ulonglong2*)(s0 + c*RS);
        ulonglong2 xa1 = *(const ulonglong2*)(s0 + c*RS + 4);
        ulonglong2 xb0 = *(const ulonglong2*)(s1 + c*RS);
        ulonglong2 xb1 = *(const ulonglong2*)(s1 + c*RS + 4);
#pragma unroll
        for (int j = 0; j < 4; j++) {
            float sv = (j==0)?s4.x:(j==1)?s4.y:(j==2)?s4.z:s4.w;
            ull p = packdup(sv);
            fma2(acc[j][0][0], p, xa0.x); fma2(acc[j][0][1], p, xa0.y);
            fma2(acc[j][0][2], p, xa1.x); fma2(acc[j][0][3], p, xa1.y);
            fma2(acc[j][1][0], p, xb0.x); fma2(acc[j][1][1], p, xb0.y);
            fma2(acc[j][1][2], p, xb1.x); fma2(acc[j][1][3], p, xb1.y);
        }
    }
#pragma unroll
    for (int j = 0; j < 4; j++)
#pragma unroll
        for (int t = 0; t < 2; t++) {
            float* o = dst + (2*tp+t)*TS + (4*rg+j)*RS + dgm;
            float2 f0=unpk(acc[j][t][0]), f1=unpk(acc[j][t][1]);
            float2 f2=unpk(acc[j][t][2]), f3=unpk(acc[j][t][3]);
            *(float4*)o     = make_float4(f0.x,f0.y,f1.x,f1.y);
            *(float4*)(o+4) = make_float4(f2.x,f2.y,f3.x,f3.y);
        }
}

template<bool ADD>
__device__ __forceinline__ void gemm2v(const float* __restrict__ src, float* __restrict__ dst,
                                       const float* __restrict__ W, const float* __restrict__ bias,
                                       int ta, int dg)
{
    ull acc[2][4];
    const ulonglong2* bp = (const ulonglong2*)(bias + dg);
    ulonglong2 b01 = bp[0], b23 = bp[1];
#pragma unroll
    for (int k = 0; k < 2; k++) { acc[k][0]=b01.x; acc[k][1]=b01.y; acc[k][2]=b23.x; acc[k][3]=b23.y; }
#pragma unroll 4
    for (int c4 = 0; c4 < 16; c4++) {
        float4 xa = *(const float4*)(src + ta*VST + c4*4);
        float4 xb = *(const float4*)(src + (ta+1)*VST + c4*4);
#pragma unroll
        for (int cc = 0; cc < 4; cc++) {
            const ulonglong2* w = (const ulonglong2*)(W + (c4*4+cc)*LAT + dg);
            ulonglong2 w01 = w[0], w23 = w[1];
            float va = (cc==0)?xa.x:(cc==1)?xa.y:(cc==2)?xa.z:xa.w;
            float vb = (cc==0)?xb.x:(cc==1)?xb.y:(cc==2)?xb.z:xb.w;
            ull pa = packdup(va), pb = packdup(vb);
            fma2(acc[0][0], pa, w01.x); fma2(acc[0][1], pa, w01.y);
            fma2(acc[0][2], pa, w23.x); fma2(acc[0][3], pa, w23.y);
            fma2(acc[1][0], pb, w01.x); fma2(acc[1][1], pb, w01.y);
            fma2(acc[1][2], pb, w23.x); fma2(acc[1][3], pb, w23.y);
        }
    }
#pragma unroll
    for (int k = 0; k < 2; k++) {
        float* o = dst + (ta+k)*VST + dg;
        float2 f0=unpk(acc[k][0]), f1=unpk(acc[k][1]), f2=unpk(acc[k][2]), f3=unpk(acc[k][3]);
        if (ADD) {
            float4 e0 = *(float4*)o, e1 = *(float4*)(o+4);
            e0.x += tanh_fast(f0.x); e0.y += tanh_fast(f0.y); e0.z += tanh_fast(f1.x); e0.w += tanh_fast(f1.y);
            e1.x += tanh_fast(f2.x); e1.y += tanh_fast(f2.y); e1.z += tanh_fast(f3.x); e1.w += tanh_fast(f3.y);
            *(float4*)o = e0; *(float4*)(o+4) = e1;
        } else {
            *(float4*)o     = make_float4(tanh_fast(f0.x),tanh_fast(f0.y),tanh_fast(f1.x),tanh_fast(f1.y));
            *(float4*)(o+4) = make_float4(tanh_fast(f2.x),tanh_fast(f2.y),tanh_fast(f3.x),tanh_fast(f3.y));
        }
    }
}

// warp-8: act mix (mix1) for 2 tiles -> vectors
__device__ __forceinline__ void mix2v(const float* __restrict__ XTb, float* __restrict__ dst,
                                      const float* __restrict__ sk, int ta, int dg)
{
    ull acc[2][4];
#pragma unroll
    for (int k = 0; k < 2; k++) { acc[k][0]=0; acc[k][1]=0; acc[k][2]=0; acc[k][3]=0; }
#pragma unroll 4
    for (int c = 0; c < VV; c++) {
        ull s2 = packdup(sk[c]);
#pragma unroll
        for (int k = 0; k < 2; k++) {
            const ulonglong2* a = (const ulonglong2*)(XTb + (ta+k)*TS + c*RS + dg);
            ulonglong2 a01 = a[0], a23 = a[1];
            fma2(acc[k][0], s2, a01.x); fma2(acc[k][1], s2, a01.y);
            fma2(acc[k][2], s2, a23.x); fma2(acc[k][3], s2, a23.y);
        }
    }
#pragma unroll
    for (int k = 0; k < 2; k++) {
        float* o = dst + (ta+k)*VST + dg;
        float2 f0=unpk(acc[k][0]), f1=unpk(acc[k][1]), f2=unpk(acc[k][2]), f3=unpk(acc[k][3]);
        *(float4*)o     = make_float4(f0.x,f0.y,f1.x,f1.y);
        *(float4*)(o+4) = make_float4(f2.x,f2.y,f3.x,f3.y);
    }
}

__device__ __forceinline__ void gemmv_o(const float* __restrict__ v,
                                        const float* __restrict__ W,
                                        const float* __restrict__ bias,
                                        int dg, float o[8])
{
    const ulonglong2* bp = (const ulonglong2*)(bias + dg);
    ulonglong2 b01 = bp[0], b23 = bp[1];
    ull a0 = b01.x, a1 = b01.y, a2 = b23.x, a3 = b23.y;
#pragma unroll 4
    for (int c4 = 0; c4 < 16; c4++) {
        float4 x = *(const float4*)(v + c4*4);
#pragma unroll
        for (int cc = 0; cc < 4; cc++) {
            float xv = (cc==0)?x.x:(cc==1)?x.y:(cc==2)?x.z:x.w;
            ull p = packdup(xv);
            const ulonglong2* w = (const ulonglong2*)(W + (c4*4+cc)*LAT + dg);
            ulonglong2 w01 = w[0], w23 = w[1];
            fma2(a0, p, w01.x); fma2(a1, p, w01.y);
            fma2(a2, p, w23.x); fma2(a3, p, w23.y);
        }
    }
    float2 f0=unpk(a0), f1=unpk(a1), f2=unpk(a2), f3=unpk(a3);
    o[0]=f0.x; o[1]=f0.y; o[2]=f1.x; o[3]=f1.y;
    o[4]=f2.x; o[5]=f2.y; o[6]=f3.x; o[7]=f3.y;
}

// smem layout (floats)
#define OFF_W2   0
#define OFF_WO   (OFF_W2 + LAT*LAT)
#define OFF_WS1  (OFF_WO + LAT*LAT)
#define OFF_WS2  (OFF_WS1 + LAT*LAT)
#define OFF_BV   (OFF_WS2 + LAT*LAT)
#define OFF_WQ   (OFF_BV + 6*LAT)
#define OFF_SK   (OFF_WQ + NBB)
#define OFF_SKT  (OFF_SK + 1092)
#define OFF_ATT  (OFF_SKT + VV*36)
#define OFF_XA   (OFF_ATT + ROWS*AO)
#define OFF_YA   (OFF_XA + 8*VST)
#define OFF_BTD  (OFF_YA + 8*VST)         // bterm double buffer [2][512]
#define OFF_X    (OFF_BTD + 1024)
#define OFF_Y    (OFF_X + 8*TS)
#define SMEM_FLOATS (OFF_Y + 8*TS)
#define SMEM_BYTES  (SMEM_FLOATS * 4)     // 228240

__global__ void __launch_bounds__(288, 1) fused_kernel(
    const float* __restrict__ phase, const float* __restrict__ boundary,
    const float* __restrict__ bweights, const float* __restrict__ vel_coords,
    const float* __restrict__ vweights, const float* __restrict__ scat,
    const float* __restrict__ self_scat,
    const float* __restrict__ pos_coords, const float* __restrict__ sigma,
    const float* __restrict__ Wq, const float* __restrict__ bq,
    const float* __restrict__ Wk, const float* __restrict__ bk,
    const float* __restrict__ Wv, const float* __restrict__ bv,
    const float* __restrict__ Wo, const float* __restrict__ bo,
    const float* __restrict__ W1, const float* __restrict__ b1,
    const float* __restrict__ W2, const float* __restrict__ b2,
    const float* __restrict__ Wout, const float* __restrict__ bout,
    const float* __restrict__ Ws1, const float* __restrict__ bs1,
    const float* __restrict__ Ws2, const float* __restrict__ bs2,
    const float* __restrict__ Wp, float* __restrict__ out)
{
    extern __shared__ float sh[];
    float* W2s  = sh + OFF_W2;
    float* Wos  = sh + OFF_WO;
    float* Ws1s = sh + OFF_WS1;
    float* Ws2s = sh + OFF_WS2;
    float* b1s  = sh + OFF_BV;
    float* b2s  = b1s + LAT;
    float* bouts= b1s + 2*LAT;
    float* bs1s = b1s + 3*LAT;
    float* bs2s = b1s + 4*LAT;
    float* Wps  = b1s + 5*LAT;
    float* wqS  = sh + OFF_WQ;
    float* SKs  = sh + OFF_SK;
    float* SKt  = sh + OFF_SKT;
    float* attS = sh + OFF_ATT;
    float* xA   = sh + OFF_XA;
    float* yA   = sh + OFF_YA;
    float* btD  = sh + OFF_BTD;
    float* XT   = sh + OFF_X;
    float* YT   = sh + OFF_Y;
    // prologue overlays
    float* bkT  = XT;
    float* vsT  = XT + 8448;
    float* rS   = XT + 16896;
    float* base1= YT;

    int tid = threadIdx.x;
    int bp = blockIdx.x;
    int b = bp / PP, p = bp % PP;

    const float* ph = phase + (b*PP+p)*4;
    float p0 = ph[0], p1 = ph[1], p2 = ph[2], p3 = ph[3];
    const float* btG = g_bterm + b*NBB*LAT;

    // ---- stage A: stage weights + build base_k / v tables ----
    for (int i = tid; i < LAT*LAT; i += 288) {
        W2s[i] = W2[i]; Wos[i] = Wout[i]; Ws1s[i] = Ws1[i]; Ws2s[i] = Ws2[i];
    }
    if (tid < LAT) {
        b1s[tid] = b1[tid]; b2s[tid] = b2[tid]; bouts[tid] = bout[tid];
        bs1s[tid] = bs1[tid]; bs2s[tid] = bs2[tid]; Wps[tid] = Wp[tid];
    }
    if (tid < NBB)
        wqS[tid] = boundary[b*NBB+tid] * bweights[b*NBB+tid];
    for (int i = tid; i < ROWS*VV; i += 288) {
        int rr = i >> 5, v = i & 31;
        float w = vweights[b*VV+v];
        float val = (rr < 32) ? (1.0f - self_scat[(b*VV+rr)*VV+v]) * w
                              : (1.0f - scat[(b*PP+p)*VV+v]) * w;
        SKs[rr*33+v] = val;
        if (rr < 32) SKt[v*36+rr] = val;
    }
    for (int i = tid; i < 512; i += 288)      // prefetch iter-0 bterm slice
        btD[i] = btG[i];
    if (tid < 256) {
        const float* pc = pos_coords + (b*TT+tid)*2;
        float r0 = pc[0] - p0, r1 = pc[1] - p1;
        rS[2*tid] = r0; rS[2*tid+1] = r1;
        const float* sg = sigma + (b*TT+tid)*2;
        float s0 = sg[0], s1 = sg[1];
#pragma unroll 8
        for (int j = 0; j < AO; j++) {
            bkT[tid*33+j] = r0*__ldg(Wk+j) + r1*__ldg(Wk+AO+j) + __ldg(bk+j);
            vsT[tid*33+j] = s0*__ldg(Wv+j) + s1*__ldg(Wv+AO+j) + __ldg(bv+j);
        }
    }
    __syncthreads();

    // ---- stage B: attention ----
    {
        int w = tid >> 5, lane = tid & 31;
        int nq = (w < 8) ? 4 : 1;
        for (int qi = 0; qi < nq; qi++) {
            int q = (w < 8) ? (w*4 + qi) : 32;
            float c2, c3;
            if (q < 32) { const float* vc = vel_coords + (b*VV+q)*2; c2 = vc[0]; c3 = vc[1]; }
            else        { c2 = p2; c3 = p3; }
            float qv = p0*__ldg(Wq+lane) + p1*__ldg(Wq+AO+lane)
                     + c2*__ldg(Wq+2*AO+lane) + c3*__ldg(Wq+3*AO+lane) + __ldg(bq+lane);
            float qcp = qv * (c2*__ldg(Wk+2*AO+lane) + c3*__ldg(Wk+3*AO+lane));
            qcp += __shfl_xor_sync(0xffffffffu, qcp, 1);
            qcp += __shfl_xor_sync(0xffffffffu, qcp, 2);
            qcp += __shfl_xor_sync(0xffffffffu, qcp, 4);
            float qch[4];
#pragma unroll
            for (int h = 0; h < 4; h++) qch[h] = __shfl_sync(0xffffffffu, qcp, h*8);
            float acc[8][4];
#pragma unroll
            for (int k = 0; k < 8; k++) { acc[k][0]=0.f; acc[k][1]=0.f; acc[k][2]=0.f; acc[k][3]=0.f; }
#pragma unroll
            for (int d = 0; d < 32; d++) {
                float qd = __shfl_sync(0xffffffffu, qv, d);
                int h = d >> 3;
#pragma unroll
                for (int k = 0; k < 8; k++)
                    acc[k][h] += qd * bkT[(lane+32*k)*33 + d];
            }
#pragma unroll
            for (int k = 0; k < 8; k++) {
                float r0 = rS[2*(lane+32*k)], r1 = rS[2*(lane+32*k)+1];
                bool valid = (r0*c2 + r1*c3) <= 0.0f;
#pragma unroll
                for (int h = 0; h < 4; h++) {
                    float l = (acc[k][h] + qch[h]) * 0.3535533905932738f;
                    acc[k][h] = valid ? l : -1e30f;
                }
            }
#pragma unroll
            for (int h = 0; h < 4; h++) {
                float mx = acc[0][h];
#pragma unroll
                for (int k = 1; k < 8; k++) mx = fmaxf(mx, acc[k][h]);
#pragma unroll
                for (int o = 16; o; o >>= 1) mx = fmaxf(mx, __shfl_xor_sync(0xffffffffu, mx, o));
                float sm = 0.f;
#pragma unroll
                for (int k = 0; k < 8; k++) { acc[k][h] = __expf(acc[k][h] - mx); sm += acc[k][h]; }
#pragma unroll
                for (int o = 16; o; o >>= 1) sm += __shfl_xor_sync(0xffffffffu, sm, o);
                float inv = __fdividef(1.0f, sm);
#pragma unroll
                for (int k = 0; k < 8; k++) acc[k][h] *= inv;
            }
            float pa[32];
#pragma unroll
            for (int d = 0; d < 32; d++) pa[d] = 0.f;
#pragma unroll
            for (int k = 0; k < 8; k++) {
                int base = (lane+32*k)*33;
#pragma unroll
                for (int d = 0; d < 32; d++)
                    pa[d] += acc[k][d>>3] * vsT[base + d];
            }
#pragma unroll
            for (int o = 16; o; o >>= 1) {
#pragma unroll
                for (int d = 0; d < 32; d++) pa[d] += __shfl_xor_sync(0xffffffffu, pa[d], o);
            }
            float ov = __ldg(bo + lane);
#pragma unroll
            for (int k2 = 0; k2 < 32; k2++) ov += pa[k2] * __ldg(Wo + k2*AO + lane);
            attS[q*AO + lane] = __expf(-ov);
        }
    }
    __syncthreads();

    // ---- stage C: base1 ----
    for (int i = tid; i < ROWS*LAT; i += 288) {
        int rr = i >> 6, d = i & 63;
        float cc2, cc3;
        if (rr < 32) { cc2 = vel_coords[(b*VV+rr)*2]; cc3 = vel_coords[(b*VV+rr)*2+1]; }
        else         { cc2 = p2; cc3 = p3; }
        const float* att = attS + rr*AO;
        float s = b1s[d] + p0*__ldg(W1+d) + p1*__ldg(W1+LAT+d)
                + cc2*__ldg(W1+2*LAT+d) + cc3*__ldg(W1+3*LAT+d);
#pragma unroll 8
        for (int j = 0; j < AO; j++) s += att[j] * __ldg(W1 + (8+j)*LAT + d);
        base1[rr*RS+d] = s;
    }
    __syncthreads();

    // thread mapping
    int r = 0, dg = 0, lane8 = 0, p8 = 0, dg8 = 0;
    if (tid < 256) { r = tid >> 3; dg = (tid & 7) << 3; }
    else { lane8 = tid - 256; p8 = lane8 >> 3; dg8 = (lane8 & 7) << 3; }
    int tp = tid >> 6, rg = (tid >> 3) & 7, dgm = (tid & 7) << 3;
    int tM = tid >> 5, jp = tid & 31;

    float baseR[8];
    {
        const float* bsrc = base1 + ((tid < 256) ? (r*RS + dg) : (32*RS + dg8));
        float4 a = *(const float4*)bsrc, c = *(const float4*)(bsrc + 4);
        baseR[0]=a.x; baseR[1]=a.y; baseR[2]=a.z; baseR[3]=a.w;
        baseR[4]=c.x; baseR[5]=c.y; baseR[6]=c.z; baseR[7]=c.w;
    }

    const float* sk32 = SKs + 32*33;
    float accOut = 0.f;
    for (int it = 0; it < NBB/8; ++it) {
        const float* btB = btD + ((it & 1) << 9);
        // ---- L1 + gemm W2 + gemm Wout ----
        if (tid < 256) {
#pragma unroll
            for (int t = 0; t < 8; t++) {
                const float* bt = btB + t*LAT + dg;
                float4 b0 = *(const float4*)bt, b1v = *(const float4*)(bt+4);
                float* xo = XT + t*TS + r*RS + dg;
                *(float4*)xo = make_float4(tanh_fast(baseR[0]+b0.x), tanh_fast(baseR[1]+b0.y),
                                           tanh_fast(baseR[2]+b0.z), tanh_fast(baseR[3]+b0.w));
                *(float4*)(xo+4) = make_float4(tanh_fast(baseR[4]+b1v.x), tanh_fast(baseR[5]+b1v.y),
                                               tanh_fast(baseR[6]+b1v.z), tanh_fast(baseR[7]+b1v.w));
            }
            __syncwarp();
            gemm8<false>(XT, YT, W2s, b2s, r, dg);
            __syncwarp();
            gemm8<false>(YT, XT, Wos, bouts, r, dg);
        } else {
            int ta = 2*p8;
#pragma unroll
            for (int k = 0; k < 2; k++) {
                const float* bt = btB + (ta+k)*LAT + dg8;
                float4 b0 = *(const float4*)bt, b1v = *(const float4*)(bt+4);
                float* xo = xA + (ta+k)*VST + dg8;
                *(float4*)xo = make_float4(tanh_fast(baseR[0]+b0.x), tanh_fast(baseR[1]+b0.y),
                                           tanh_fast(baseR[2]+b0.z), tanh_fast(baseR[3]+b0.w));
                *(float4*)(xo+4) = make_float4(tanh_fast(baseR[4]+b1v.x), tanh_fast(baseR[5]+b1v.y),
                                               tanh_fast(baseR[6]+b1v.z), tanh_fast(baseR[7]+b1v.w));
            }
            __syncwarp();
            gemm2v<false>(xA, yA, W2s, b2s, ta, dg8);
            __syncwarp();
            gemm2v<false>(yA, xA, Wos, bouts, ta, dg8);
        }
        __syncthreads();                 // (1) XT tiles complete for mix 1
        if (tid < 256) {
            mixMR(XT, YT, SKt, rg, tp, dgm);
        } else {
            mix2v(XT, yA, sk32, 2*p8, dg8);
        }
        // prefetch next iteration's bterm slice into the other buffer
        if (it + 1 < NBB/8) {
            float* dstb = btD + (((it+1) & 1) << 9);
            const float* srcb = btG + (it+1)*512;
            for (int i = tid; i < 512; i += 288) dstb[i] = srcb[i];
        }
        __syncthreads();                 // (2) mix1 reads of XT done (+ prefetch visible)
        if (tid < 256) {
            gemm8<true>(YT, XT, Ws1s, bs1s, r, dg);
        } else {
            gemm2v<true>(yA, xA, Ws1s, bs1s, 2*p8, dg8);
        }
        __syncthreads();                 // (3) post-Ws1 XT complete
        if (tid < 256) {
            const float* xb = XT + tM*TS + 2*jp;
            ull acc = 0;
#pragma unroll 8
            for (int c = 0; c < VV; c++) {
                ull xv = *(const ull*)(xb + c*RS);
                fma2(acc, packdup(sk32[c]), xv);
            }
            *(ull*)(yA + tM*VST + 2*jp) = acc;
        }
        __syncthreads();                 // (4) XT free for next iter; yA act-mix2 ready
        if (tid >= 256) {
            int ta = 2*p8;
            int nb0 = it*8;
#pragma unroll
            for (int k = 0; k < 2; k++) {
                float o[8]; gemmv_o(yA + (ta+k)*VST, Ws2s, bs2s, dg8, o);
                const float* xr = xA + (ta+k)*VST + dg8;
                float s = 0.f;
#pragma unroll
                for (int i = 0; i < 8; i++)
                    s += (xr[i] + tanh_fast(o[i])) * Wps[dg8+i];
                s += __shfl_xor_sync(0xffffffffu, s, 1);
                s += __shfl_xor_sync(0xffffffffu, s, 2);
                s += __shfl_xor_sync(0xffffffffu, s, 4);
                if ((lane8 & 7) == 0)
                    accOut += __expf(s) * wqS[nb0 + ta + k];
            }
        }
    }
    if (tid >= 256) {
        accOut += __shfl_xor_sync(0xffffffffu, accOut, 8);
        accOut += __shfl_xor_sync(0xffffffffu, accOut, 16);
        if (lane8 == 0) out[bp] = accOut;
    }
}

extern "C" void kernel_launch(void* const* d_in, const int* in_sizes, int n_in,
                              void* d_out, int out_size)
{
    const float* phase   = (const float*)d_in[0];
    const float* bcoords = (const float*)d_in[1];
    const float* boundary= (const float*)d_in[2];
    const float* bweights= (const float*)d_in[3];
    const float* poscrd  = (const float*)d_in[4];
    const float* sigma   = (const float*)d_in[5];
    const float* velcrd  = (const float*)d_in[6];
    const float* vweights= (const float*)d_in[7];
    const float* scat    = (const float*)d_in[8];
    const float* sscat   = (const float*)d_in[9];
    const float* Wq = (const float*)d_in[10]; const float* bq = (const float*)d_in[11];
    const float* Wk = (const float*)d_in[12]; const float* bk = (const float*)d_in[13];
    const float* Wv = (const float*)d_in[14]; const float* bv = (const float*)d_in[15];
    const float* Wo = (const float*)d_in[16]; const float* bo = (const float*)d_in[17];
    const float* W1 = (const float*)d_in[18]; const float* b1 = (const float*)d_in[19];
    const float* W2 = (const float*)d_in[20]; const float* b2 = (const float*)d_in[21];
    const float* Wout = (const float*)d_in[22]; const float* bout = (const float*)d_in[23];
    const float* Ws1 = (const float*)d_in[24]; const float* bs1 = (const float*)d_in[25];
    const float* Ws2 = (const float*)d_in[26]; const float* bs2 = (const float*)d_in[27];
    const float* Wp = (const float*)d_in[28];
    float* out = (float*)d_out;

    cudaFuncSetAttribute(fused_kernel,
                         cudaFuncAttributeMaxDynamicSharedMemorySize, SMEM_BYTES);

    prep_kernel<<<BB*NBB, LAT>>>(bcoords, W1);
    fused_kernel<<<BB*PP, 288, SMEM_BYTES>>>(
        phase, boundary, bweights, velcrd, vweights, scat, sscat,
        poscrd, sigma, Wq, bq, Wk, bk, Wv, bv, Wo, bo,
        W1, b1, W2, b2, Wout, bout, Ws1, bs1, Ws2, bs2, Wp, out);
}

// round 17
// speedup vs baseline: 1.0363x; 1.0363x over previous
#include <cuda_runtime.h>
#include <math.h>

#define BB  2
#define PP  64
#define NBB 64
#define TT  256
#define VV  32
#define HH  4
#define AO  32
#define LAT 64
#define RS  68
#define ROWS 33
#define TS  (32*RS)
#define VST 68

typedef unsigned long long ull;

__device__ float g_bterm[BB*NBB*LAT];

__device__ __forceinline__ float tanh_fast(float x) {
    float y; asm("tanh.approx.f32 %0,%1;" : "=f"(y) : "f"(x)); return y;
}
__device__ __forceinline__ ull packdup(float x) {
    ull r; asm("mov.b64 %0,{%1,%1};" : "=l"(r) : "f"(x)); return r;
}
__device__ __forceinline__ void fma2(ull& d, ull a, ull b) {
    asm("fma.rn.f32x2 %0,%1,%2,%0;" : "+l"(d) : "l"(a), "l"(b));
}
__device__ __forceinline__ float2 unpk(ull a) {
    float2 f; asm("mov.b64 {%0,%1},%2;" : "=f"(f.x), "=f"(f.y) : "l"(a)); return f;
}

// ---------------- prep: boundary term table ----------------------------------
__global__ void prep_kernel(const float* __restrict__ bcoords,
                            const float* __restrict__ W1) {
    int bn = blockIdx.x, d = threadIdx.x;
    const float* bc = bcoords + bn * 4;
    g_bterm[bn*LAT + d] = bc[0]*W1[4*LAT+d] + bc[1]*W1[5*LAT+d]
                        + bc[2]*W1[6*LAT+d] + bc[3]*W1[7*LAT+d];
}

// ---------------- fused kernel helpers ---------------------------------------
// MODE 0: out = tanh(bias + X@W); MODE 2: out = X@W raw (no bias)
template<int MODE>
__device__ __forceinline__ void gemm8(const float* __restrict__ src, float* __restrict__ dst,
                                      const float* __restrict__ W, const float* __restrict__ bias,
                                      int r, int dg)
{
    ull acc[8][4];
    if (MODE == 0) {
        const ulonglong2* bp = (const ulonglong2*)(bias + dg);
        ulonglong2 b01 = bp[0], b23 = bp[1];
#pragma unroll
        for (int t = 0; t < 8; t++) { acc[t][0]=b01.x; acc[t][1]=b01.y; acc[t][2]=b23.x; acc[t][3]=b23.y; }
    } else {
#pragma unroll
        for (int t = 0; t < 8; t++) { acc[t][0]=0; acc[t][1]=0; acc[t][2]=0; acc[t][3]=0; }
    }
    const float* row = src + r*RS;
#pragma unroll 2
    for (int c4 = 0; c4 < 16; c4++) {
        float4 x[8];
#pragma unroll
        for (int t = 0; t < 8; t++) x[t] = *(const float4*)(row + t*TS + c4*4);
#pragma unroll
        for (int cc = 0; cc < 4; cc++) {
            const ulonglong2* w = (const ulonglong2*)(W + (c4*4+cc)*LAT + dg);
            ulonglong2 w01 = w[0], w23 = w[1];
#pragma unroll
            for (int t = 0; t < 8; t++) {
                float xv = (cc==0)?x[t].x:(cc==1)?x[t].y:(cc==2)?x[t].z:x[t].w;
                ull p = packdup(xv);
                fma2(acc[t][0], p, w01.x); fma2(acc[t][1], p, w01.y);
                fma2(acc[t][2], p, w23.x); fma2(acc[t][3], p, w23.y);
            }
        }
    }
#pragma unroll
    for (int t = 0; t < 8; t++) {
        float* o = dst + t*TS + r*RS + dg;
        if (MODE == 0) {
            float2 f0=unpk(acc[t][0]), f1=unpk(acc[t][1]), f2=unpk(acc[t][2]), f3=unpk(acc[t][3]);
            *(float4*)o     = make_float4(tanh_fast(f0.x),tanh_fast(f0.y),tanh_fast(f1.x),tanh_fast(f1.y));
            *(float4*)(o+4) = make_float4(tanh_fast(f2.x),tanh_fast(f2.y),tanh_fast(f3.x),tanh_fast(f3.y));
        } else {
            ulonglong2* ov = (ulonglong2*)o;
            ov[0] = make_ulonglong2(acc[t][0], acc[t][1]);
            ov[1] = make_ulonglong2(acc[t][2], acc[t][3]);
        }
    }
}

// fused mix+tanh+add: X[4rg+j][2tp+t] += tanh(SK[4rg+j]·M + bs1), M = Y tiles
__device__ __forceinline__ void mixtanhMR(const float* __restrict__ M, float* __restrict__ X,
                                          const float* __restrict__ SKt, const float* __restrict__ bias,
                                          int rg, int tp, int dgm)
{
    ull acc[4][2][4];
#pragma unroll
    for (int j = 0; j < 4; j++)
#pragma unroll
        for (int t = 0; t < 2; t++) {
            acc[j][t][0]=0; acc[j][t][1]=0; acc[j][t][2]=0; acc[j][t][3]=0;
        }
    const float* s0 = M + (2*tp)*TS + dgm;
    const float* s1 = M + (2*tp+1)*TS + dgm;
#pragma unroll 4
    for (int c = 0; c < VV; c++) {
        float4 s4 = *(const float4*)(SKt + c*36 + 4*rg);
        ulonglong2 xa0 = *(const ulonglong2*)(s0 + c*RS);
        ulonglong2 xa1 = *(const ulonglong2*)(s0 + c*RS + 4);
        ulonglong2 xb0 = *(const ulonglong2*)(s1 + c*RS);
        ulonglong2 xb1 = *(const ulonglong2*)(s1 + c*RS + 4);
#pragma unroll
        for (int j = 0; j < 4; j++) {
            float sv = (j==0)?s4.x:(j==1)?s4.y:(j==2)?s4.z:s4.w;
            ull p = packdup(sv);
            fma2(acc[j][0][0], p, xa0.x); fma2(acc[j][0][1], p, xa0.y);
            fma2(acc[j][0][2], p, xa1.x); fma2(acc[j][0][3], p, xa1.y);
            fma2(acc[j][1][0], p, xb0.x); fma2(acc[j][1][1], p, xb0.y);
            fma2(acc[j][1][2], p, xb1.x); fma2(acc[j][1][3], p, xb1.y);
        }
    }
    float4 bb0 = *(const float4*)(bias + dgm);
    float4 bb1 = *(const float4*)(bias + dgm + 4);
#pragma unroll
    for (int j = 0; j < 4; j++)
#pragma unroll
        for (int t = 0; t < 2; t++) {
            float* o = X + (2*tp+t)*TS + (4*rg+j)*RS + dgm;
            float2 f0=unpk(acc[j][t][0]), f1=unpk(acc[j][t][1]);
            float2 f2=unpk(acc[j][t][2]), f3=unpk(acc[j][t][3]);
            float4 e0 = *(float4*)o, e1 = *(float4*)(o+4);
            e0.x += tanh_fast(f0.x+bb0.x); e0.y += tanh_fast(f0.y+bb0.y);
            e0.z += tanh_fast(f1.x+bb0.z); e0.w += tanh_fast(f1.y+bb0.w);
            e1.x += tanh_fast(f2.x+bb1.x); e1.y += tanh_fast(f2.y+bb1.y);
            e1.z += tanh_fast(f3.x+bb1.z); e1.w += tanh_fast(f3.y+bb1.w);
            *(float4*)o = e0; *(float4*)(o+4) = e1;
        }
}

template<bool ADD>
__device__ __forceinline__ void gemm2v(const float* __restrict__ src, float* __restrict__ dst,
                                       const float* __restrict__ W, const float* __restrict__ bias,
                                       int ta, int dg)
{
    ull acc[2][4];
    const ulonglong2* bp = (const ulonglong2*)(bias + dg);
    ulonglong2 b01 = bp[0], b23 = bp[1];
#pragma unroll
    for (int k = 0; k < 2; k++) { acc[k][0]=b01.x; acc[k][1]=b01.y; acc[k][2]=b23.x; acc[k][3]=b23.y; }
#pragma unroll 4
    for (int c4 = 0; c4 < 16; c4++) {
        float4 xa = *(const float4*)(src + ta*VST + c4*4);
        float4 xb = *(const float4*)(src + (ta+1)*VST + c4*4);
#pragma unroll
        for (int cc = 0; cc < 4; cc++) {
            const ulonglong2* w = (const ulonglong2*)(W + (c4*4+cc)*LAT + dg);
            ulonglong2 w01 = w[0], w23 = w[1];
            float va = (cc==0)?xa.x:(cc==1)?xa.y:(cc==2)?xa.z:xa.w;
            float vb = (cc==0)?xb.x:(cc==1)?xb.y:(cc==2)?xb.z:xb.w;
            ull pa = packdup(va), pb = packdup(vb);
            fma2(acc[0][0], pa, w01.x); fma2(acc[0][1], pa, w01.y);
            fma2(acc[0][2], pa, w23.x); fma2(acc[0][3], pa, w23.y);
            fma2(acc[1][0], pb, w01.x); fma2(acc[1][1], pb, w01.y);
            fma2(acc[1][2], pb, w23.x); fma2(acc[1][3], pb, w23.y);
        }
    }
#pragma unroll
    for (int k = 0; k < 2; k++) {
        float* o = dst + (ta+k)*VST + dg;
        float2 f0=unpk(acc[k][0]), f1=unpk(acc[k][1]), f2=unpk(acc[k][2]), f3=unpk(acc[k][3]);
        if (ADD) {
            float4 e0 = *(float4*)o, e1 = *(float4*)(o+4);
            e0.x += tanh_fast(f0.x); e0.y += tanh_fast(f0.y); e0.z += tanh_fast(f1.x); e0.w += tanh_fast(f1.y);
            e1.x += tanh_fast(f2.x); e1.y += tanh_fast(f2.y); e1.z += tanh_fast(f3.x); e1.w += tanh_fast(f3.y);
            *(float4*)o = e0; *(float4*)(o+4) = e1;
        } else {
            *(float4*)o     = make_float4(tanh_fast(f0.x),tanh_fast(f0.y),tanh_fast(f1.x),tanh_fast(f1.y));
            *(float4*)(o+4) = make_float4(tanh_fast(f2.x),tanh_fast(f2.y),tanh_fast(f3.x),tanh_fast(f3.y));
        }
    }
}

// warp-8: act Ws1 update via shared M: xA[ta+k] += tanh(SK32·M + bs1)
__device__ __forceinline__ void mixtanh2v(const float* __restrict__ Mtiles, float* __restrict__ xAv,
                                          const float* __restrict__ sk, const float* __restrict__ bias,
                                          int ta, int dg)
{
    ull acc[2][4];
#pragma unroll
    for (int k = 0; k < 2; k++) { acc[k][0]=0; acc[k][1]=0; acc[k][2]=0; acc[k][3]=0; }
#pragma unroll 4
    for (int c = 0; c < VV; c++) {
        ull s2 = packdup(sk[c]);
#pragma unroll
        for (int k = 0; k < 2; k++) {
            const ulonglong2* a = (const ulonglong2*)(Mtiles + (ta+k)*TS + c*RS + dg);
            ulonglong2 a01 = a[0], a23 = a[1];
            fma2(acc[k][0], s2, a01.x); fma2(acc[k][1], s2, a01.y);
            fma2(acc[k][2], s2, a23.x); fma2(acc[k][3], s2, a23.y);
        }
    }
    float4 bb0 = *(const float4*)(bias + dg);
    float4 bb1 = *(const float4*)(bias + dg + 4);
#pragma unroll
    for (int k = 0; k < 2; k++) {
        float* o = xAv + (ta+k)*VST + dg;
        float2 f0=unpk(acc[k][0]), f1=unpk(acc[k][1]), f2=unpk(acc[k][2]), f3=unpk(acc[k][3]);
        float4 e0 = *(float4*)o, e1 = *(float4*)(o+4);
        e0.x += tanh_fast(f0.x+bb0.x); e0.y += tanh_fast(f0.y+bb0.y);
        e0.z += tanh_fast(f1.x+bb0.z); e0.w += tanh_fast(f1.y+bb0.w);
        e1.x += tanh_fast(f2.x+bb1.x); e1.y += tanh_fast(f2.y+bb1.y);
        e1.z += tanh_fast(f3.x+bb1.z); e1.w += tanh_fast(f3.y+bb1.w);
        *(float4*)o = e0; *(float4*)(o+4) = e1;
    }
}

__device__ __forceinline__ void gemmv_o(const float* __restrict__ v,
                                        const float* __restrict__ W,
                                        const float* __restrict__ bias,
                                        int dg, float o[8])
{
    const ulonglong2* bp = (const ulonglong2*)(bias + dg);
    ulonglong2 b01 = bp[0], b23 = bp[1];
    ull a0 = b01.x, a1 = b01.y, a2 = b23.x, a3 = b23.y;
#pragma unroll 4
    for (int c4 = 0; c4 < 16; c4++) {
        float4 x = *(const float4*)(v + c4*4);
#pragma unroll
        for (int cc = 0; cc < 4; cc++) {
            float xv = (cc==0)?x.x:(cc==1)?x.y:(cc==2)?x.z:x.w;
            ull p = packdup(xv);
            const ulonglong2* w = (const ulonglong2*)(W + (c4*4+cc)*LAT + dg);
            ulonglong2 w01 = w[0], w23 = w[1];
            fma2(a0, p, w01.x); fma2(a1, p, w01.y);
            fma2(a2, p, w23.x); fma2(a3, p, w23.y);
        }
    }
    float2 f0=unpk(a0), f1=unpk(a1), f2=unpk(a2), f3=unpk(a3);
    o[0]=f0.x; o[1]=f0.y; o[2]=f1.x; o[3]=f1.y;
    o[4]=f2.x; o[5]=f2.y; o[6]=f3.x; o[7]=f3.y;
}

// smem layout (floats)
#define OFF_W2   0
#define OFF_WO   (OFF_W2 + LAT*LAT)
#define OFF_WS1  (OFF_WO + LAT*LAT)
#define OFF_WS2  (OFF_WS1 + LAT*LAT)
#define OFF_BV   (OFF_WS2 + LAT*LAT)
#define OFF_WQ   (OFF_BV + 6*LAT)
#define OFF_SK   (OFF_WQ + NBB)
#define OFF_SKT  (OFF_SK + 1092)
#define OFF_ATT  (OFF_SKT + VV*36)
#define OFF_XA   (OFF_ATT + ROWS*AO)
#define OFF_YA   (OFF_XA + 8*VST)
#define OFF_X    (OFF_YA + 8*VST)
#define OFF_Y    (OFF_X + 8*TS)
#define SMEM_FLOATS (OFF_Y + 8*TS)
#define SMEM_BYTES  (SMEM_FLOATS * 4)     // 224144

__global__ void __launch_bounds__(288, 1) fused_kernel(
    const float* __restrict__ phase, const float* __restrict__ boundary,
    const float* __restrict__ bweights, const float* __restrict__ vel_coords,
    const float* __restrict__ vweights, const float* __restrict__ scat,
    const float* __restrict__ self_scat,
    const float* __restrict__ pos_coords, const float* __restrict__ sigma,
    const float* __restrict__ Wq, const float* __restrict__ bq,
    const float* __restrict__ Wk, const float* __restrict__ bk,
    const float* __restrict__ Wv, const float* __restrict__ bv,
    const float* __restrict__ Wo, const float* __restrict__ bo,
    const float* __restrict__ W1, const float* __restrict__ b1,
    const float* __restrict__ W2, const float* __restrict__ b2,
    const float* __restrict__ Wout, const float* __restrict__ bout,
    const float* __restrict__ Ws1, const float* __restrict__ bs1,
    const float* __restrict__ Ws2, const float* __restrict__ bs2,
    const float* __restrict__ Wp, float* __restrict__ out)
{
    extern __shared__ float sh[];
    float* W2s  = sh + OFF_W2;
    float* Wos  = sh + OFF_WO;
    float* Ws1s = sh + OFF_WS1;
    float* Ws2s = sh + OFF_WS2;
    float* b1s  = sh + OFF_BV;
    float* b2s  = b1s + LAT;
    float* bouts= b1s + 2*LAT;
    float* bs1s = b1s + 3*LAT;
    float* bs2s = b1s + 4*LAT;
    float* Wps  = b1s + 5*LAT;
    float* wqS  = sh + OFF_WQ;
    float* SKs  = sh + OFF_SK;
    float* SKt  = sh + OFF_SKT;
    float* attS = sh + OFF_ATT;
    float* xA   = sh + OFF_XA;
    float* yA   = sh + OFF_YA;
    float* XT   = sh + OFF_X;
    float* YT   = sh + OFF_Y;
    // prologue overlays
    float* bkT  = XT;
    float* vsT  = XT + 8448;
    float* rS   = XT + 16896;
    float* base1= YT;

    int tid = threadIdx.x;
    int bp = blockIdx.x;
    int b = bp / PP, p = bp % PP;

    const float* ph = phase + (b*PP+p)*4;
    float p0 = ph[0], p1 = ph[1], p2 = ph[2], p3 = ph[3];
    const float* btG = g_bterm + b*NBB*LAT;

    // ---- stage A ----
    for (int i = tid; i < LAT*LAT; i += 288) {
        W2s[i] = W2[i]; Wos[i] = Wout[i]; Ws1s[i] = Ws1[i]; Ws2s[i] = Ws2[i];
    }
    if (tid < LAT) {
        b1s[tid] = b1[tid]; b2s[tid] = b2[tid]; bouts[tid] = bout[tid];
        bs1s[tid] = bs1[tid]; bs2s[tid] = bs2[tid]; Wps[tid] = Wp[tid];
    }
    if (tid < NBB)
        wqS[tid] = boundary[b*NBB+tid] * bweights[b*NBB+tid];
    for (int i = tid; i < ROWS*VV; i += 288) {
        int rr = i >> 5, v = i & 31;
        float w = vweights[b*VV+v];
        float val = (rr < 32) ? (1.0f - self_scat[(b*VV+rr)*VV+v]) * w
                              : (1.0f - scat[(b*PP+p)*VV+v]) * w;
        SKs[rr*33+v] = val;
        if (rr < 32) SKt[v*36+rr] = val;
    }
    if (tid < 256) {
        const float* pc = pos_coords + (b*TT+tid)*2;
        float r0 = pc[0] - p0, r1 = pc[1] - p1;
        rS[2*tid] = r0; rS[2*tid+1] = r1;
        const float* sg = sigma + (b*TT+tid)*2;
        float s0 = sg[0], s1 = sg[1];
#pragma unroll 8
        for (int j = 0; j < AO; j++) {
            bkT[tid*33+j] = r0*__ldg(Wk+j) + r1*__ldg(Wk+AO+j) + __ldg(bk+j);
            vsT[tid*33+j] = s0*__ldg(Wv+j) + s1*__ldg(Wv+AO+j) + __ldg(bv+j);
        }
    }
    __syncthreads();

    // ---- stage B: attention ----
    {
        int w = tid >> 5, lane = tid & 31;
        int nq = (w < 8) ? 4 : 1;
        for (int qi = 0; qi < nq; qi++) {
            int q = (w < 8) ? (w*4 + qi) : 32;
            float c2, c3;
            if (q < 32) { const float* vc = vel_coords + (b*VV+q)*2; c2 = vc[0]; c3 = vc[1]; }
            else        { c2 = p2; c3 = p3; }
            float qv = p0*__ldg(Wq+lane) + p1*__ldg(Wq+AO+lane)
                     + c2*__ldg(Wq+2*AO+lane) + c3*__ldg(Wq+3*AO+lane) + __ldg(bq+lane);
            float qcp = qv * (c2*__ldg(Wk+2*AO+lane) + c3*__ldg(Wk+3*AO+lane));
            qcp += __shfl_xor_sync(0xffffffffu, qcp, 1);
            qcp += __shfl_xor_sync(0xffffffffu, qcp, 2);
            qcp += __shfl_xor_sync(0xffffffffu, qcp, 4);
            float qch[4];
#pragma unroll
            for (int h = 0; h < 4; h++) qch[h] = __shfl_sync(0xffffffffu, qcp, h*8);
            float acc[8][4];
#pragma unroll
            for (int k = 0; k < 8; k++) { acc[k][0]=0.f; acc[k][1]=0.f; acc[k][2]=0.f; acc[k][3]=0.f; }
#pragma unroll
            for (int d = 0; d < 32; d++) {
                float qd = __shfl_sync(0xffffffffu, qv, d);
                int h = d >> 3;
#pragma unroll
                for (int k = 0; k < 8; k++)
                    acc[k][h] += qd * bkT[(lane+32*k)*33 + d];
            }
#pragma unroll
            for (int k = 0; k < 8; k++) {
                float r0 = rS[2*(lane+32*k)], r1 = rS[2*(lane+32*k)+1];
                bool valid = (r0*c2 + r1*c3) <= 0.0f;
#pragma unroll
                for (int h = 0; h < 4; h++) {
                    float l = (acc[k][h] + qch[h]) * 0.3535533905932738f;
                    acc[k][h] = valid ? l : -1e30f;
                }
            }
#pragma unroll
            for (int h = 0; h < 4; h++) {
                float mx = acc[0][h];
#pragma unroll
                for (int k = 1; k < 8; k++) mx = fmaxf(mx, acc[k][h]);
#pragma unroll
                for (int o = 16; o; o >>= 1) mx = fmaxf(mx, __shfl_xor_sync(0xffffffffu, mx, o));
                float sm = 0.f;
#pragma unroll
                for (int k = 0; k < 8; k++) { acc[k][h] = __expf(acc[k][h] - mx); sm += acc[k][h]; }
#pragma unroll
                for (int o = 16; o; o >>= 1) sm += __shfl_xor_sync(0xffffffffu, sm, o);
                float inv = __fdividef(1.0f, sm);
#pragma unroll
                for (int k = 0; k < 8; k++) acc[k][h] *= inv;
            }
            float pa[32];
#pragma unroll
            for (int d = 0; d < 32; d++) pa[d] = 0.f;
#pragma unroll
            for (int k = 0; k < 8; k++) {
                int base = (lane+32*k)*33;
#pragma unroll
                for (int d = 0; d < 32; d++)
                    pa[d] += acc[k][d>>3] * vsT[base + d];
            }
#pragma unroll
            for (int o = 16; o; o >>= 1) {
#pragma unroll
                for (int d = 0; d < 32; d++) pa[d] += __shfl_xor_sync(0xffffffffu, pa[d], o);
            }
            float ov = __ldg(bo + lane);
#pragma unroll
            for (int k2 = 0; k2 < 32; k2++) ov += pa[k2] * __ldg(Wo + k2*AO + lane);
            attS[q*AO + lane] = __expf(-ov);
        }
    }
    __syncthreads();

    // ---- stage C: base1 ----
    for (int i = tid; i < ROWS*LAT; i += 288) {
        int rr = i >> 6, d = i & 63;
        float cc2, cc3;
        if (rr < 32) { cc2 = vel_coords[(b*VV+rr)*2]; cc3 = vel_coords[(b*VV+rr)*2+1]; }
        else         { cc2 = p2; cc3 = p3; }
        const float* att = attS + rr*AO;
        float s = b1s[d] + p0*__ldg(W1+d) + p1*__ldg(W1+LAT+d)
                + cc2*__ldg(W1+2*LAT+d) + cc3*__ldg(W1+3*LAT+d);
#pragma unroll 8
        for (int j = 0; j < AO; j++) s += att[j] * __ldg(W1 + (8+j)*LAT + d);
        base1[rr*RS+d] = s;
    }
    __syncthreads();

    // thread mapping
    int r = 0, dg = 0, lane8 = 0, p8 = 0, dg8 = 0;
    if (tid < 256) { r = tid >> 3; dg = (tid & 7) << 3; }
    else { lane8 = tid - 256; p8 = lane8 >> 3; dg8 = (lane8 & 7) << 3; }
    int tp = tid >> 6, rg = (tid >> 3) & 7, dgm = (tid & 7) << 3;
    int tM = tid >> 5, jp = tid & 31;

    float baseR[8];
    {
        const float* bsrc = base1 + ((tid < 256) ? (r*RS + dg) : (32*RS + dg8));
        float4 a = *(const float4*)bsrc, c = *(const float4*)(bsrc + 4);
        baseR[0]=a.x; baseR[1]=a.y; baseR[2]=a.z; baseR[3]=a.w;
        baseR[4]=c.x; baseR[5]=c.y; baseR[6]=c.z; baseR[7]=c.w;
    }

    const float* sk32 = SKs + 32*33;
    float accOut = 0.f;
    for (int it = 0; it < NBB/8; ++it) {
        int nb0 = it*8;
        // ---- barrier-free row-local front: L1, W2, Wout, Ws1-gemm (M) ----
        if (tid < 256) {
#pragma unroll
            for (int t = 0; t < 8; t++) {
                const float* bt = btG + (nb0+t)*LAT + dg;
                float4 b0 = *(const float4*)bt, b1v = *(const float4*)(bt+4);
                float* xo = XT + t*TS + r*RS + dg;
                *(float4*)xo = make_float4(tanh_fast(baseR[0]+b0.x), tanh_fast(baseR[1]+b0.y),
                                           tanh_fast(baseR[2]+b0.z), tanh_fast(baseR[3]+b0.w));
                *(float4*)(xo+4) = make_float4(tanh_fast(baseR[4]+b1v.x), tanh_fast(baseR[5]+b1v.y),
                                               tanh_fast(baseR[6]+b1v.z), tanh_fast(baseR[7]+b1v.w));
            }
            __syncwarp();
            gemm8<0>(XT, YT, W2s, b2s, r, dg);       // layer 2
            __syncwarp();
            gemm8<0>(YT, XT, Wos, bouts, r, dg);     // layer 3
            __syncwarp();
            gemm8<2>(XT, YT, Ws1s, bs1s, r, dg);     // M = X @ Ws1 (raw)
        } else {
            int ta = 2*p8;
#pragma unroll
            for (int k = 0; k < 2; k++) {
                const float* bt = btG + (nb0+ta+k)*LAT + dg8;
                float4 b0 = *(const float4*)bt, b1v = *(const float4*)(bt+4);
                float* xo = xA + (ta+k)*VST + dg8;
                *(float4*)xo = make_float4(tanh_fast(baseR[0]+b0.x), tanh_fast(baseR[1]+b0.y),
                                           tanh_fast(baseR[2]+b0.z), tanh_fast(baseR[3]+b0.w));
                *(float4*)(xo+4) = make_float4(tanh_fast(baseR[4]+b1v.x), tanh_fast(baseR[5]+b1v.y),
                                               tanh_fast(baseR[6]+b1v.z), tanh_fast(baseR[7]+b1v.w));
            }
            __syncwarp();
            gemm2v<false>(xA, yA, W2s, b2s, ta, dg8);
            __syncwarp();
            gemm2v<false>(yA, xA, Wos, bouts, ta, dg8);
        }
        __syncthreads();                 // (a) M (Y tiles) + post-Wout X complete
        // ---- fused mix1+Ws1 update ----
        if (tid < 256) {
            mixtanhMR(YT, XT, SKt, bs1s, rg, tp, dgm);
        } else {
            mixtanh2v(YT, xA, sk32, bs1s, 2*p8, dg8);
        }
        __syncthreads();                 // (b) post-Ws1 X complete
        // ---- act mix2 (parallel, 256 threads) ----
        if (tid < 256) {
            const float* xb = XT + tM*TS + 2*jp;
            ull acc = 0;
#pragma unroll 8
            for (int c = 0; c < VV; c++) {
                ull xv = *(const ull*)(xb + c*RS);
                fma2(acc, packdup(sk32[c]), xv);
            }
            *(ull*)(yA + tM*VST + 2*jp) = acc;
        }
        __syncthreads();                 // (c) XT free; yA act-mix2 ready
        // ---- warp-8 tail (overlaps next iteration's front) ----
        if (tid >= 256) {
            int ta = 2*p8;
#pragma unroll
            for (int k = 0; k < 2; k++) {
                float o[8]; gemmv_o(yA + (ta+k)*VST, Ws2s, bs2s, dg8, o);
                const float* xr = xA + (ta+k)*VST + dg8;
                float s = 0.f;
#pragma unroll
                for (int i = 0; i < 8; i++)
                    s += (xr[i] + tanh_fast(o[i])) * Wps[dg8+i];
                s += __shfl_xor_sync(0xffffffffu, s, 1);
                s += __shfl_xor_sync(0xffffffffu, s, 2);
                s += __shfl_xor_sync(0xffffffffu, s, 4);
                if ((lane8 & 7) == 0)
                    accOut += __expf(s) * wqS[nb0 + ta + k];
            }
        }
    }
    if (tid >= 256) {
        accOut += __shfl_xor_sync(0xffffffffu, accOut, 8);
        accOut += __shfl_xor_sync(0xffffffffu, accOut, 16);
        if (lane8 == 0) out[bp] = accOut;
    }
}

extern "C" void kernel_launch(void* const* d_in, const int* in_sizes, int n_in,
                              void* d_out, int out_size)
{
    const float* phase   = (const float*)d_in[0];
    const float* bcoords = (const float*)d_in[1];
    const float* boundary= (const float*)d_in[2];
    const float* bweights= (const float*)d_in[3];
    const float* poscrd  = (const float*)d_in[4];
    const float* sigma   = (const float*)d_in[5];
    const float* velcrd  = (const float*)d_in[6];
    const float* vweights= (const float*)d_in[7];
    const float* scat    = (const float*)d_in[8];
    const float* sscat   = (const float*)d_in[9];
    const float* Wq = (const float*)d_in[10]; const float* bq = (const float*)d_in[11];
    const float* Wk = (const float*)d_in[12]; const float* bk = (const float*)d_in[13];
    const float* Wv = (const float*)d_in[14]; const float* bv = (const float*)d_in[15];
    const float* Wo = (const float*)d_in[16]; const float* bo = (const float*)d_in[17];
    const float* W1 = (const float*)d_in[18]; const float* b1 = (const float*)d_in[19];
    const float* W2 = (const float*)d_in[20]; const float* b2 = (const float*)d_in[21];
    const float* Wout = (const float*)d_in[22]; const float* bout = (const float*)d_in[23];
    const float* Ws1 = (const float*)d_in[24]; const float* bs1 = (const float*)d_in[25];
    const float* Ws2 = (const float*)d_in[26]; const float* bs2 = (const float*)d_in[27];
    const float* Wp = (const float*)d_in[28];
    float* out = (float*)d_out;

    cudaFuncSetAttribute(fused_kernel,
                         cudaFuncAttributeMaxDynamicSharedMemorySize, SMEM_BYTES);

    prep_kernel<<<BB*NBB, LAT>>>(bcoords, W1);
    fused_kernel<<<BB*PP, 288, SMEM_BYTES>>>(
        phase, boundary, bweights, velcrd, vweights, scat, sscat,
        poscrd, sigma, Wq, bq, Wk, bk, Wv, bv, Wo, bo,
        W1, b1, W2, b2, Wout, bout, Ws1, bs1, Ws2, bs2, Wp, out);
}